// round 16
// baseline (speedup 1.0000x reference)
#include <cuda_runtime.h>
#include <cuda_bf16.h>
#include <cstdint>
#include <math.h>

#define NROWS   8192
#define DIM     128
#define KSLAB   64                   // rows per inner slab
#define NINNER  2                    // inner slabs per block (K=128)
#define NSLABO  (NROWS / (KSLAB * NINNER))   // 64 outer slabs
#define NTASK   (3 * NSLABO)         // 192 blocks
#define PITCH   136                  // bf16 pitch: 17x16B, ldmatrix conflict-free
#define NKSTEP  (KSLAB / 16)         // 4

#define TILE_BYTES (KSLAB * PITCH * 2)   // 17408
#define GSMEM      (2 * TILE_BYTES)      // 34816 -> 2 CTAs/SM by smem
#define KSTEP_B    (16 * PITCH * 2)      // 4352 bytes per k16 step

#define RBLK 512                     // reduce grid (proven shape)
#define RTHR 256

// ---------------- device globals (no allocs allowed) ----------------------
__device__ float    g_part[3][NSLABO][DIM * DIM]; // 12.6 MB partial grams
__device__ double   g_loss;
__device__ unsigned g_tick;

__device__ __forceinline__ uint32_t smem_u32(const void* p) {
    uint32_t a;
    asm("{ .reg .u64 t; cvta.to.shared.u64 t, %1; cvt.u32.u64 %0, t; }"
        : "=r"(a) : "l"(p));
    return a;
}

#define LDMX4T(r0, r1, r2, r3, addr) \
    asm volatile("ldmatrix.sync.aligned.m8n8.x4.trans.shared.b16 {%0,%1,%2,%3}, [%4];" \
        : "=r"(r0), "=r"(r1), "=r"(r2), "=r"(r3) : "r"(addr))

#define MMA16816(d, a, b0, b1) \
    asm volatile("mma.sync.aligned.m16n8k16.row.col.f32.bf16.bf16.f32 " \
        "{%0,%1,%2,%3}, {%4,%5,%6,%7}, {%8,%9}, {%0,%1,%2,%3};" \
        : "+f"((d)[0]), "+f"((d)[1]), "+f"((d)[2]), "+f"((d)[3]) \
        : "r"((a)[0]), "r"((a)[1]), "r"((a)[2]), "r"((a)[3]), \
          "r"(b0), "r"(b1))

// normalize 64x128 f32 slab -> bf16 tile, NATURAL [row][dim] layout.
// 256 threads (8 warps): warp w owns rows (b*4+i)*8+w; two batches of 4
// front-batched float4 loads (MLP=4, keeps regs under the 2-CTA cap).
__device__ __forceinline__ void build_tile(const float* __restrict__ src,
                                           __nv_bfloat16* dst,
                                           int lane, int w)
{
    const float4* s4 = reinterpret_cast<const float4*>(src);
#pragma unroll
    for (int b = 0; b < 2; b++) {
        float4 v[4];
#pragma unroll
        for (int i = 0; i < 4; i++)          // row = (b*4+i)*8 + w
            v[i] = s4[((b * 4 + i) * 8 + w) * 32 + lane];
#pragma unroll
        for (int i = 0; i < 4; i++) {
            float s = v[i].x * v[i].x + v[i].y * v[i].y
                    + v[i].z * v[i].z + v[i].w * v[i].w;
#pragma unroll
            for (int off = 16; off > 0; off >>= 1)
                s += __shfl_xor_sync(0xffffffffu, s, off);
            float inv = 1.0f / fmaxf(sqrtf(s), 1e-8f);
            __nv_bfloat162 h0 = __floats2bfloat162_rn(v[i].x * inv, v[i].y * inv);
            __nv_bfloat162 h1 = __floats2bfloat162_rn(v[i].z * inv, v[i].w * inv);
            uint2 pk = { *reinterpret_cast<const uint32_t*>(&h0),
                         *reinterpret_cast<const uint32_t*>(&h1) };
            *reinterpret_cast<uint2*>(
                &dst[((b * 4 + i) * 8 + w) * PITCH + lane * 4]) = pk;
        }
    }
}

// ---- kernel 1: gram tasks, K-split, 2 CTAs/SM -----------------------------
// grid = 192: gram = bid>>6 (0=QQ,1=KK,2=QK), oslab = bid&63. 256 threads.
// Warp tile 32(m) x 64(n): m0 = (w&3)*32, n0 = (w>>2)*64. Full 128x128 out.
extern "C" __global__ void __launch_bounds__(256, 2)
gram_kernel(const float* __restrict__ Q, const float* __restrict__ K)
{
    extern __shared__ char smem[];
    __nv_bfloat16* tA = reinterpret_cast<__nv_bfloat16*>(smem);
    __nv_bfloat16* tB = tA + KSLAB * PITCH;
    const uint32_t sAaddr = smem_u32(tA);
    const uint32_t sBaddr = smem_u32(tB);

    const int t     = threadIdx.x;
    const int lane  = t & 31;
    const int w     = t >> 5;
    const int gram  = blockIdx.x >> 6;
    const int oslab = blockIdx.x & 63;

    const float* srcA = (gram == 1) ? K : Q;
    const size_t base = (size_t)oslab * NINNER * KSLAB * DIM;

    const int m0 = (w & 3) * 32;
    const int n0 = (w >> 2) * 64;
    const int gi = lane >> 3, gj = lane & 7;
    const uint32_t aOff = (uint32_t)((((gi >> 1) * 8 + gj) * PITCH + (gi & 1) * 8) * 2);
    const uint32_t bOff = (uint32_t)((((gi & 1) * 8 + gj) * PITCH + (gi >> 1) * 8) * 2);
    const uint32_t aBase = sAaddr + aOff + (uint32_t)(m0 * 2);
    const uint32_t bBase = ((gram == 2) ? sBaddr : sAaddr) + bOff + (uint32_t)(n0 * 2);

    float acc[2][4][2][4];   // [mt][nt4][lo/hi][4] -- accumulates both slabs
#pragma unroll
    for (int mt = 0; mt < 2; mt++)
#pragma unroll
        for (int n4 = 0; n4 < 4; n4++)
#pragma unroll
            for (int h = 0; h < 2; h++)
#pragma unroll
                for (int r = 0; r < 4; r++) acc[mt][n4][h][r] = 0.0f;

#pragma unroll
    for (int is = 0; is < NINNER; is++) {
        const size_t sb = base + (size_t)is * KSLAB * DIM;
        build_tile(srcA + sb, tA, lane, w);
        if (gram == 2)
            build_tile(K + sb, tB, lane, w);
        __syncthreads();

        // single-buffered frags; 16 warps/SM provide the latency hiding
#pragma unroll
        for (int ks = 0; ks < NKSTEP; ks++) {
            const uint32_t kOff = (uint32_t)ks * KSTEP_B;
            uint32_t a[2][4];
#pragma unroll
            for (int mt = 0; mt < 2; mt++)
                LDMX4T(a[mt][0], a[mt][1], a[mt][2], a[mt][3],
                       aBase + kOff + (uint32_t)(mt * 32));
            uint32_t b[4][4];
#pragma unroll
            for (int n4 = 0; n4 < 4; n4++)
                LDMX4T(b[n4][0], b[n4][1], b[n4][2], b[n4][3],
                       bBase + kOff + (uint32_t)(n4 * 32));
#pragma unroll
            for (int mt = 0; mt < 2; mt++)
#pragma unroll
                for (int n4 = 0; n4 < 4; n4++) {
                    MMA16816(acc[mt][n4][0], a[mt], b[n4][0], b[n4][1]);
                    MMA16816(acc[mt][n4][1], a[mt], b[n4][2], b[n4][3]);
                }
        }
        __syncthreads();   // all ldmatrix reads done before next build_tile
    }

    // thread-private contiguous store: 16 x STG.128, uniform permutation
    float* outp = &g_part[gram][oslab][0] + (size_t)t * 64;
#pragma unroll
    for (int mt = 0; mt < 2; mt++)
#pragma unroll
        for (int n4 = 0; n4 < 4; n4++)
#pragma unroll
            for (int h = 0; h < 2; h++)
                *reinterpret_cast<float4*>(outp + mt * 32 + n4 * 8 + h * 4)
                    = *reinterpret_cast<const float4*>(acc[mt][n4][h]);
}

// ---- kernel 2: wide reduce (proven 512x256 shape, now 64 slabs) -----------
// entry = bid*32+lane (coalesced); warp w owns slabs w*8..w*8+7 (24 LDG).
// Full 64-slab sums assembled in smem BEFORE squaring (regrouping exact).
extern "C" __global__ void __launch_bounds__(RTHR)
reduce_kernel(float* __restrict__ out)
{
    const int t    = threadIdx.x;
    const int lane = t & 31;
    const int w    = t >> 5;
    const int entry = blockIdx.x * 32 + lane;          // [0, 16384)
    const float* p0 = &g_part[0][0][0];
    const float* p1 = &g_part[1][0][0];
    const float* p2 = &g_part[2][0][0];

    float sq = 0.0f, sk = 0.0f, sx = 0.0f;
#pragma unroll
    for (int s = 0; s < 8; s++) {
        const int off = (w * 8 + s) * 16384 + entry;
        sq += p0[off];
        sk += p1[off];
        sx += p2[off];
    }

    __shared__ float sQ[8][32], sK[8][32], sX[8][32];
    sQ[w][lane] = sq; sK[w][lane] = sk; sX[w][lane] = sx;
    __syncthreads();

    if (w == 0) {
        float q = 0.0f, k = 0.0f, x = 0.0f;
#pragma unroll
        for (int ww = 0; ww < 8; ww++) {
            q += sQ[ww][lane];
            k += sK[ww][lane];
            x += sX[ww][lane];
        }
        double dq = (double)q, dk = (double)k, dx = (double)x;
        double c = dq * dq + dk * dk - 2.0 * dx * dx;
#pragma unroll
        for (int off = 16; off > 0; off >>= 1)
            c += __shfl_xor_sync(0xffffffffu, c, off);

        if (lane == 0) {
            atomicAdd(&g_loss, c);
            __threadfence();
            unsigned tk = atomicAdd(&g_tick, 1u);
            if (tk == RBLK - 1u) {       // last block: all adds visible
                double L = *(volatile double*)&g_loss;
                out[0] = (float)(L / (8192.0 * 8191.0));
                g_loss = 0.0;            // self-reset for next graph replay
                __threadfence();
                g_tick = 0u;
            }
        }
    }
}

extern "C" void kernel_launch(void* const* d_in, const int* in_sizes, int n_in,
                              void* d_out, int out_size)
{
    (void)in_sizes; (void)n_in; (void)out_size;
    const float* Q = (const float*)d_in[0];
    const float* K = (const float*)d_in[1];

    cudaFuncSetAttribute(gram_kernel,
                         cudaFuncAttributeMaxDynamicSharedMemorySize, GSMEM);

    gram_kernel<<<NTASK, 256, GSMEM>>>(Q, K);
    reduce_kernel<<<RBLK, RTHR>>>((float*)d_out);
}

// round 17
// speedup vs baseline: 1.6656x; 1.6656x over previous
#include <cuda_runtime.h>
#include <cuda_bf16.h>
#include <cuda_fp16.h>
#include <cstdint>
#include <math.h>

#define NROWS   8192
#define DIM     128
#define KSLAB   64                   // rows per inner slab
#define NINNER  4                    // inner slabs accumulated per block (K=256)
#define NSLABO  (NROWS / (KSLAB * NINNER))   // 32 outer slabs
#define NTASK   (3 * NSLABO)         // 96 blocks
#define PITCH   136                  // bf16 pitch: 17x16B, ldmatrix conflict-free
#define NKSTEP  (KSLAB / 16)         // 4

#define TILE_BYTES (KSLAB * PITCH * 2)   // 17408
#define GSMEM      (2 * TILE_BYTES)      // 34816
#define KSTEP_B    (16 * PITCH * 2)      // 4352 bytes per k16 step

#define RBLK 256                     // reduce grid: half2 pair = bid*32+lane
#define RTHR 256                     // 8 warps: warp w owns slabs w*4..w*4+3

// ---------------- device globals (no allocs allowed) ----------------------
__device__ __half   g_part[3][NSLABO][DIM * DIM]; // 3.15 MB fp16 partials
__device__ double   g_loss;
__device__ unsigned g_tick;

__device__ __forceinline__ uint32_t smem_u32(const void* p) {
    uint32_t a;
    asm("{ .reg .u64 t; cvta.to.shared.u64 t, %1; cvt.u32.u64 %0, t; }"
        : "=r"(a) : "l"(p));
    return a;
}

#define LDMX4T(r0, r1, r2, r3, addr) \
    asm volatile("ldmatrix.sync.aligned.m8n8.x4.trans.shared.b16 {%0,%1,%2,%3}, [%4];" \
        : "=r"(r0), "=r"(r1), "=r"(r2), "=r"(r3) : "r"(addr))

#define MMA16816(d, a, b0, b1) \
    asm volatile("mma.sync.aligned.m16n8k16.row.col.f32.bf16.bf16.f32 " \
        "{%0,%1,%2,%3}, {%4,%5,%6,%7}, {%8,%9}, {%0,%1,%2,%3};" \
        : "+f"((d)[0]), "+f"((d)[1]), "+f"((d)[2]), "+f"((d)[3]) \
        : "r"((a)[0]), "r"((a)[1]), "r"((a)[2]), "r"((a)[3]), \
          "r"(b0), "r"(b1))

// gmem slab -> registers (front-batched, MLP=4 per matrix)
__device__ __forceinline__ void load_slab(const float* __restrict__ src,
                                          float4 v[4], int lane, int w)
{
    const float4* s4 = reinterpret_cast<const float4*>(src);
#pragma unroll
    for (int i = 0; i < 4; i++)                  // row = i*16 + w, col = lane*4
        v[i] = s4[(i * 16 + w) * 32 + lane];
}

// registers -> normalized bf16 tile in NATURAL [row][dim] layout
__device__ __forceinline__ void store_tile(const float4 v[4],
                                           __nv_bfloat16* dst, int lane, int w)
{
#pragma unroll
    for (int i = 0; i < 4; i++) {
        float s = v[i].x * v[i].x + v[i].y * v[i].y
                + v[i].z * v[i].z + v[i].w * v[i].w;
#pragma unroll
        for (int off = 16; off > 0; off >>= 1)
            s += __shfl_xor_sync(0xffffffffu, s, off);
        float inv = 1.0f / fmaxf(sqrtf(s), 1e-8f);
        __nv_bfloat162 h0 = __floats2bfloat162_rn(v[i].x * inv, v[i].y * inv);
        __nv_bfloat162 h1 = __floats2bfloat162_rn(v[i].z * inv, v[i].w * inv);
        uint2 pk = { *reinterpret_cast<const uint32_t*>(&h0),
                     *reinterpret_cast<const uint32_t*>(&h1) };
        *reinterpret_cast<uint2*>(&dst[(i * 16 + w) * PITCH + lane * 4]) = pk;
    }
}

// ---- kernel 1: gram tasks (round-11 structure; fp16 partial store) --------
// grid = 96: gram = bid/32 (0=QQ,1=KK,2=QK), oslab = bid%32. 512 threads.
extern "C" __global__ void __launch_bounds__(512, 1)
gram_kernel(const float* __restrict__ Q, const float* __restrict__ K)
{
    extern __shared__ char smem[];
    __nv_bfloat16* tA = reinterpret_cast<__nv_bfloat16*>(smem);
    __nv_bfloat16* tB = tA + KSLAB * PITCH;
    const uint32_t sAaddr = smem_u32(tA);
    const uint32_t sBaddr = smem_u32(tB);

    const int t     = threadIdx.x;
    const int lane  = t & 31;
    const int w     = t >> 5;
    const int gram  = blockIdx.x >> 5;
    const int oslab = blockIdx.x & 31;

    const float* srcA = (gram == 1) ? K : Q;
    const size_t base = (size_t)oslab * NINNER * KSLAB * DIM;

    // warp tile: 32 M-rows x 32 N-cols (4x4 warp grid)
    const int m0 = (w & 3) * 32;
    const int n0 = (w >> 2) * 32;
    const int gi = lane >> 3, gj = lane & 7;
    const uint32_t aOff = (uint32_t)((((gi >> 1) * 8 + gj) * PITCH + (gi & 1) * 8) * 2);
    const uint32_t bOff = (uint32_t)((((gi & 1) * 8 + gj) * PITCH + (gi >> 1) * 8) * 2);
    const uint32_t aBase = sAaddr + aOff + (uint32_t)(m0 * 2);
    const uint32_t bBase = ((gram == 2) ? sBaddr : sAaddr) + bOff + (uint32_t)(n0 * 2);

    float acc[2][2][2][4];   // [mt][n4][nt(lo/hi)][4] -- accumulates ALL slabs
#pragma unroll
    for (int mt = 0; mt < 2; mt++)
#pragma unroll
        for (int n4 = 0; n4 < 2; n4++)
#pragma unroll
            for (int nt = 0; nt < 2; nt++)
#pragma unroll
                for (int r = 0; r < 4; r++) acc[mt][n4][nt][r] = 0.0f;

    float4 vA[4], vB[4];
    load_slab(srcA + base, vA, lane, w);
    if (gram == 2) load_slab(K + base, vB, lane, w);

#pragma unroll
    for (int is = 0; is < NINNER; is++) {
        store_tile(vA, tA, lane, w);
        if (gram == 2) store_tile(vB, tB, lane, w);
        __syncthreads();

        // prefetch next slab while MMAs run on this one
        if (is + 1 < NINNER) {
            const size_t nb = base + (size_t)(is + 1) * KSLAB * DIM;
            load_slab(srcA + nb, vA, lane, w);
            if (gram == 2) load_slab(K + nb, vB, lane, w);
        }

        // double-buffered fragment pipeline over 4 ksteps
        uint32_t a[2][2][4], b[2][2][4];
#pragma unroll
        for (int mt = 0; mt < 2; mt++)
            LDMX4T(a[0][mt][0], a[0][mt][1], a[0][mt][2], a[0][mt][3],
                   aBase + (uint32_t)(mt * 32));
#pragma unroll
        for (int n4 = 0; n4 < 2; n4++)
            LDMX4T(b[0][n4][0], b[0][n4][1], b[0][n4][2], b[0][n4][3],
                   bBase + (uint32_t)(n4 * 32));

#pragma unroll
        for (int ks = 0; ks < NKSTEP; ks++) {
            const int cur = ks & 1, nxt = cur ^ 1;
            if (ks + 1 < NKSTEP) {
                const uint32_t kOff = (uint32_t)(ks + 1) * KSTEP_B;
#pragma unroll
                for (int mt = 0; mt < 2; mt++)
                    LDMX4T(a[nxt][mt][0], a[nxt][mt][1], a[nxt][mt][2], a[nxt][mt][3],
                           aBase + kOff + (uint32_t)(mt * 32));
#pragma unroll
                for (int n4 = 0; n4 < 2; n4++)
                    LDMX4T(b[nxt][n4][0], b[nxt][n4][1], b[nxt][n4][2], b[nxt][n4][3],
                           bBase + kOff + (uint32_t)(n4 * 32));
            }
#pragma unroll
            for (int mt = 0; mt < 2; mt++)
#pragma unroll
                for (int n4 = 0; n4 < 2; n4++) {
                    MMA16816(acc[mt][n4][0], a[cur][mt], b[cur][n4][0], b[cur][n4][1]);
                    MMA16816(acc[mt][n4][1], a[cur][mt], b[cur][n4][2], b[cur][n4][3]);
                }
        }
        __syncthreads();   // all ldmatrix reads done before next store_tile
    }

    // fp16 partial store: thread t owns halfs [t*32, t*32+32) = 4 x STG.128,
    // same uniform permutation every task -> reduce regrouping stays exact
    __half* outp = &g_part[gram][oslab][0] + (size_t)t * 32;
#pragma unroll
    for (int mt = 0; mt < 2; mt++)
#pragma unroll
        for (int n4 = 0; n4 < 2; n4++) {
            const float* lo = acc[mt][n4][0];
            const float* hi = acc[mt][n4][1];
            uint4 pk;
            __half2 h;
            h = __floats2half2_rn(lo[0], lo[1]); pk.x = *reinterpret_cast<uint32_t*>(&h);
            h = __floats2half2_rn(lo[2], lo[3]); pk.y = *reinterpret_cast<uint32_t*>(&h);
            h = __floats2half2_rn(hi[0], hi[1]); pk.z = *reinterpret_cast<uint32_t*>(&h);
            h = __floats2half2_rn(hi[2], hi[3]); pk.w = *reinterpret_cast<uint32_t*>(&h);
            *reinterpret_cast<uint4*>(outp + mt * 16 + n4 * 8) = pk;
        }
}

// ---- kernel 2: half2 wide reduce ------------------------------------------
// 256 blocks x 256 thr: half2 pair p = bid*32+lane (coalesced 128B/warp);
// warp w owns slabs w*4..w*4+3 -> 12 half2 LDGs per thread, 2 entries each.
// Full 32-slab fp32 sums assembled BEFORE squaring (regrouping exact).
extern "C" __global__ void __launch_bounds__(RTHR)
reduce_kernel(float* __restrict__ out)
{
    const int t    = threadIdx.x;
    const int lane = t & 31;
    const int w    = t >> 5;
    const int p    = blockIdx.x * 32 + lane;           // [0, 8192) pair idx
    const __half2* p2 = reinterpret_cast<const __half2*>(&g_part[0][0][0]);
    // half2 view: [gram*32 + slab][8192]

    float2 sq = {0.f, 0.f}, sk = {0.f, 0.f}, sx = {0.f, 0.f};
#pragma unroll
    for (int s = 0; s < 4; s++) {
        const int slab = w * 4 + s;
        float2 a = __half22float2(p2[(0 * 32 + slab) * 8192 + p]);
        float2 b = __half22float2(p2[(1 * 32 + slab) * 8192 + p]);
        float2 c = __half22float2(p2[(2 * 32 + slab) * 8192 + p]);
        sq.x += a.x; sq.y += a.y;
        sk.x += b.x; sk.y += b.y;
        sx.x += c.x; sx.y += c.y;
    }

    __shared__ float2 sQ[8][32], sK[8][32], sX[8][32];
    sQ[w][lane] = sq; sK[w][lane] = sk; sX[w][lane] = sx;
    __syncthreads();

    if (w == 0) {
        float2 q = {0.f, 0.f}, k = {0.f, 0.f}, x = {0.f, 0.f};
#pragma unroll
        for (int ww = 0; ww < 8; ww++) {
            float2 a = sQ[ww][lane], b = sK[ww][lane], c = sX[ww][lane];
            q.x += a.x; q.y += a.y;
            k.x += b.x; k.y += b.y;
            x.x += c.x; x.y += c.y;
        }
        double c = 0.0;
        {
            double dq = (double)q.x, dk = (double)k.x, dx = (double)x.x;
            c += dq * dq + dk * dk - 2.0 * dx * dx;
            dq = (double)q.y; dk = (double)k.y; dx = (double)x.y;
            c += dq * dq + dk * dk - 2.0 * dx * dx;
        }
#pragma unroll
        for (int off = 16; off > 0; off >>= 1)
            c += __shfl_xor_sync(0xffffffffu, c, off);

        if (lane == 0) {
            atomicAdd(&g_loss, c);
            __threadfence();
            unsigned tk = atomicAdd(&g_tick, 1u);
            if (tk == RBLK - 1u) {       // last block: all adds visible
                double L = *(volatile double*)&g_loss;
                out[0] = (float)(L / (8192.0 * 8191.0));
                g_loss = 0.0;            // self-reset for next graph replay
                __threadfence();
                g_tick = 0u;
            }
        }
    }
}

extern "C" void kernel_launch(void* const* d_in, const int* in_sizes, int n_in,
                              void* d_out, int out_size)
{
    (void)in_sizes; (void)n_in; (void)out_size;
    const float* Q = (const float*)d_in[0];
    const float* K = (const float*)d_in[1];

    cudaFuncSetAttribute(gram_kernel,
                         cudaFuncAttributeMaxDynamicSharedMemorySize, GSMEM);

    gram_kernel<<<NTASK, 512, GSMEM>>>(Q, K);
    reduce_kernel<<<RBLK, RTHR>>>((float*)d_out);
}